// round 5
// baseline (speedup 1.0000x reference)
#include <cuda_runtime.h>
#include <cuda_bf16.h>
#include <math.h>

// Problem constants
#define BB 64
#define TT 1000
#define NN 512
#define G3 1536
#define GRID_SCAN 128

// ---------------------------------------------------------------------------
// f32x2 packed-FMA helpers (ptxas never auto-fuses; PTX-only path)
// ---------------------------------------------------------------------------
__device__ __forceinline__ unsigned long long dup2(float x) {
    unsigned long long r;
    asm("mov.b64 %0, {%1, %1};" : "=l"(r) : "f"(x));
    return r;
}
__device__ __forceinline__ void fma2(unsigned long long& d,
                                     unsigned long long a,
                                     unsigned long long b) {
    asm("fma.rn.f32x2 %0, %1, %2, %0;" : "+l"(d) : "l"(a), "l"(b));
}
__device__ __forceinline__ float2 unpack2(unsigned long long v) {
    float2 f;
    asm("mov.b64 {%0, %1}, %2;" : "=f"(f.x), "=f"(f.y) : "l"(v));
    return f;
}

// ---------------------------------------------------------------------------
// Scratch (device globals: allocation-free per harness rules)
// ---------------------------------------------------------------------------
__device__ float    g_xproj[(size_t)BB * TT * G3];  // [B][T][3N]
__device__ float    g_ht[2][NN * BB];               // TRANSPOSED hidden: [k][b]
__device__ unsigned g_count;
__device__ unsigned g_gen;

// ---------------------------------------------------------------------------
// Init: reset barrier + zero h0 (runs every graph replay)
// ---------------------------------------------------------------------------
__global__ void init_kernel() {
    int i = blockIdx.x * blockDim.x + threadIdx.x;
    if (i == 0) { g_count = 0u; g_gen = 0u; }
    for (int j = i; j < NN * BB; j += gridDim.x * blockDim.x) g_ht[0][j] = 0.0f;
}

// ---------------------------------------------------------------------------
// Kernel 1: x_proj = h_enc @ W_ih^T + b_ih.  128x128x16 tiles, 8x8 microtile,
// j-dimension packed into f32x2 (32 FFMA2/k/thread instead of 64 FFMA).
// ---------------------------------------------------------------------------
__global__ void __launch_bounds__(256) xproj_kernel(
    const float* __restrict__ A,     // [64000][512]
    const float* __restrict__ Wih,   // [1536][512]
    const float* __restrict__ bih,   // [1536]
    float* __restrict__ C)           // [64000][1536]
{
    __shared__ float As[16][128];
    __shared__ float Bs[16][128];

    const int tid   = threadIdx.x;
    const int mBase = blockIdx.y * 128;
    const int nBase = blockIdx.x * 128;
    const int tx = tid & 15;
    const int ty = tid >> 4;

    unsigned long long acc2[8][4];   // [i][j-pair]
#pragma unroll
    for (int i = 0; i < 8; i++)
#pragma unroll
        for (int j = 0; j < 4; j++) acc2[i][j] = 0ull;

    const int lr = tid >> 2;
    const int lk = (tid & 3) << 2;
    const float* Aptr = A   + (size_t)(mBase + lr) * NN + lk;
    const float* Bptr = Wih + (size_t)(nBase + lr) * NN + lk;

    for (int kt = 0; kt < NN; kt += 16) {
        const float4 a0 = *(const float4*)(Aptr + kt);
        const float4 a1 = *(const float4*)(Aptr + 64 * NN + kt);
        const float4 b0 = *(const float4*)(Bptr + kt);
        const float4 b1 = *(const float4*)(Bptr + 64 * NN + kt);
        __syncthreads();
        As[lk + 0][lr] = a0.x; As[lk + 1][lr] = a0.y; As[lk + 2][lr] = a0.z; As[lk + 3][lr] = a0.w;
        As[lk + 0][64 + lr] = a1.x; As[lk + 1][64 + lr] = a1.y; As[lk + 2][64 + lr] = a1.z; As[lk + 3][64 + lr] = a1.w;
        Bs[lk + 0][lr] = b0.x; Bs[lk + 1][lr] = b0.y; Bs[lk + 2][lr] = b0.z; Bs[lk + 3][lr] = b0.w;
        Bs[lk + 0][64 + lr] = b1.x; Bs[lk + 1][64 + lr] = b1.y; Bs[lk + 2][64 + lr] = b1.z; Bs[lk + 3][64 + lr] = b1.w;
        __syncthreads();
#pragma unroll
        for (int k = 0; k < 16; k++) {
            float af[8];
            *(float4*)&af[0] = *(const float4*)&As[k][ty * 4];
            *(float4*)&af[4] = *(const float4*)&As[k][64 + ty * 4];
            unsigned long long b2[4];
            *(uint4*)&b2[0] = *(const uint4*)&Bs[k][tx * 4];       // j 0..3
            *(uint4*)&b2[2] = *(const uint4*)&Bs[k][64 + tx * 4];  // j 4..7
#pragma unroll
            for (int i = 0; i < 8; i++) {
                const unsigned long long ad = dup2(af[i]);
#pragma unroll
                for (int j = 0; j < 4; j++) fma2(acc2[i][j], ad, b2[j]);
            }
        }
    }

    float bias[8];
#pragma unroll
    for (int j = 0; j < 8; j++) {
        int col = nBase + ((j < 4) ? (tx * 4 + j) : (64 + tx * 4 + (j - 4)));
        bias[j] = __ldg(&bih[col]);
    }
#pragma unroll
    for (int i = 0; i < 8; i++) {
        float a[8];
#pragma unroll
        for (int j = 0; j < 4; j++) {
            const float2 v = unpack2(acc2[i][j]);
            a[2 * j] = v.x; a[2 * j + 1] = v.y;
        }
        int row = mBase + ((i < 4) ? (ty * 4 + i) : (64 + ty * 4 + (i - 4)));
        float* cp = C + (size_t)row * G3 + nBase;
        *(float4*)(cp + tx * 4) =
            make_float4(a[0] + bias[0], a[1] + bias[1], a[2] + bias[2], a[3] + bias[3]);
        *(float4*)(cp + 64 + tx * 4) =
            make_float4(a[4] + bias[4], a[5] + bias[5], a[6] + bias[6], a[7] + bias[7]);
    }
}

// ---------------------------------------------------------------------------
// Kernel 2: persistent cooperative GRU scan over TRANSPOSED h.
//   128 CTAs x 256 threads. CTA owns n-cols [n0, n0+4). thread=(kq,nn,b4):
//   k-range kq*128..+127, 4 batches b4*4..+3, 3 gates -> 6 f32x2 accumulators.
//   h loads coalesced (h_t[k][b] layout, 2 wavefronts/warp-load).
// ---------------------------------------------------------------------------
__global__ void __launch_bounds__(256) gru_scan_kernel(
    const float* __restrict__ Whh,   // [1536][512]
    const float* __restrict__ bhh,   // [1536]
    float* __restrict__ out)         // [B][T][N]
{
    __shared__ float  ws[12][516];        // W_hh slice, padded rows (bank split)
    __shared__ float  xs[3][4][64];       // x_t: [gate][nn][b]
    __shared__ float4 red[4][3][4][16];   // partials: [kq][gate][nn][b4]
    __shared__ float  hs[4][64];          // h_new: [nn][b]

    const int tid = threadIdx.x;
    const int n0  = blockIdx.x * 4;
    const int kq  = tid >> 6;
    const int nn  = (tid >> 4) & 3;
    const int b4  = tid & 15;

    // Load W_hh slice once (coalesced float4 along k)
    for (int i = tid; i < 12 * 128; i += 256) {
        const int row = i >> 7;            // gate*4 + jn
        const int c4  = i & 127;
        const int gate = row >> 2;
        const int jn   = row & 3;
        const float4 v = __ldg((const float4*)(Whh + (size_t)(gate * NN + n0 + jn) * NN) + c4);
        *(float4*)&ws[row][c4 * 4] = v;
    }

    // Per-(nn) biases for the epilogue threads (tid < 64: nn=tid>>4, b4=tid&15)
    float bhr = 0.f, bhz = 0.f, bhn = 0.f;
    if (tid < 64) {
        const int en = tid >> 4;
        bhr = __ldg(&bhh[n0 + en]);
        bhz = __ldg(&bhh[NN + n0 + en]);
        bhn = __ldg(&bhh[2 * NN + n0 + en]);
    }

    const float* wr = &ws[nn][kq * 128];
    const float* wz = &ws[4 + nn][kq * 128];
    const float* wn = &ws[8 + nn][kq * 128];
    __syncthreads();

    for (int t = 0; t < TT; t++) {
        const float* hcur = g_ht[t & 1];
        float*       hnxt = g_ht[(t & 1) ^ 1];

        // Stage x_proj[:, t, slice] into SMEM (overlaps with GEMM latency)
        if (tid < 192) {
            const int grp = tid >> 6;
            const int bb  = tid & 63;
            const float4 xv = __ldg((const float4*)(
                g_xproj + (size_t)(bb * TT + t) * G3 + grp * NN + n0));
            xs[grp][0][bb] = xv.x; xs[grp][1][bb] = xv.y;
            xs[grp][2][bb] = xv.z; xs[grp][3][bb] = xv.w;
        }

        // Partial gates over this thread's k-range (f32x2 packed)
        unsigned long long ar01 = 0ull, ar23 = 0ull;
        unsigned long long az01 = 0ull, az23 = 0ull;
        unsigned long long an01 = 0ull, an23 = 0ull;
        const float* hk = hcur + kq * 128 * BB + b4 * 4;
#pragma unroll 8
        for (int k = 0; k < 128; k++) {
            const ulonglong2 hv = *(const ulonglong2*)(hk + k * BB);
            const unsigned long long wr2 = dup2(wr[k]);
            const unsigned long long wz2 = dup2(wz[k]);
            const unsigned long long wn2 = dup2(wn[k]);
            fma2(ar01, hv.x, wr2); fma2(ar23, hv.y, wr2);
            fma2(az01, hv.x, wz2); fma2(az23, hv.y, wz2);
            fma2(an01, hv.x, wn2); fma2(an23, hv.y, wn2);
        }
        {
            float2 a = unpack2(ar01), b = unpack2(ar23);
            red[kq][0][nn][b4] = make_float4(a.x, a.y, b.x, b.y);
            a = unpack2(az01); b = unpack2(az23);
            red[kq][1][nn][b4] = make_float4(a.x, a.y, b.x, b.y);
            a = unpack2(an01); b = unpack2(an23);
            red[kq][2][nn][b4] = make_float4(a.x, a.y, b.x, b.y);
        }
        __syncthreads();

        // Epilogue: 64 threads, each finishes 4 batches for one n-column
        if (tid < 64) {
            const int en = tid >> 4;
            const int eb = tid & 15;
            float4 ar = red[0][0][en][eb], az = red[0][1][en][eb], an = red[0][2][en][eb];
#pragma unroll
            for (int q = 1; q < 4; q++) {
                const float4 r0 = red[q][0][en][eb];
                const float4 r1 = red[q][1][en][eb];
                const float4 r2 = red[q][2][en][eb];
                ar.x += r0.x; ar.y += r0.y; ar.z += r0.z; ar.w += r0.w;
                az.x += r1.x; az.y += r1.y; az.z += r1.z; az.w += r1.w;
                an.x += r2.x; an.y += r2.y; an.z += r2.z; an.w += r2.w;
            }
            const float4 hp = *(const float4*)(hcur + (n0 + en) * BB + eb * 4);
            const float4 xr = *(const float4*)&xs[0][en][eb * 4];
            const float4 xz = *(const float4*)&xs[1][en][eb * 4];
            const float4 xn = *(const float4*)&xs[2][en][eb * 4];
            const float arr[4] = { xr.x + ar.x, xr.y + ar.y, xr.z + ar.z, xr.w + ar.w };
            const float azz[4] = { xz.x + az.x, xz.y + az.y, xz.z + az.z, xz.w + az.w };
            const float ann[4] = { an.x, an.y, an.z, an.w };
            const float xnn[4] = { xn.x, xn.y, xn.z, xn.w };
            const float hpp[4] = { hp.x, hp.y, hp.z, hp.w };
#pragma unroll
            for (int j = 0; j < 4; j++) {
                const float r  = 1.0f / (1.0f + __expf(-(arr[j] + bhr)));
                const float z  = 1.0f / (1.0f + __expf(-(azz[j] + bhz)));
                const float nv = tanhf(xnn[j] + r * (ann[j] + bhn));
                hs[en][eb * 4 + j] = (1.0f - z) * nv + z * hpp[j];
            }
        }
        __syncthreads();

        // Writeback: out (n-contiguous float4 per batch) + transposed h state
        if (tid < 64) {
            const int b = tid;
            *(float4*)(out + (size_t)(b * TT + t) * NN + n0) =
                make_float4(hs[0][b], hs[1][b], hs[2][b], hs[3][b]);
            const int rr = tid >> 4, seg = tid & 15;
            *(float4*)(hnxt + (n0 + rr) * BB + seg * 4) = *(const float4*)&hs[rr][seg * 4];
            __threadfence();   // release h_new before barrier arrival
        }
        __syncthreads();

        // Grid barrier (monotonic counter; 128 co-resident CTAs)
        if (t < TT - 1) {
            if (tid == 0) {
                const unsigned target = (unsigned)(t + 1);
                const unsigned arrived = atomicAdd(&g_count, 1u) + 1u;
                if (arrived == target * (unsigned)GRID_SCAN) {
                    atomicExch(&g_gen, target);
                } else {
                    volatile unsigned* vg = &g_gen;
                    while (*vg < target) { }
                }
            }
            __syncthreads();
            __threadfence();   // acquire: see other CTAs' h writes
        }
    }
}

// ---------------------------------------------------------------------------
// Launch
// ---------------------------------------------------------------------------
extern "C" void kernel_launch(void* const* d_in, const int* in_sizes, int n_in,
                              void* d_out, int out_size) {
    const float* h_enc = (const float*)d_in[0];
    const float* W_ih  = (const float*)d_in[1];
    const float* W_hh  = (const float*)d_in[2];
    const float* b_ih  = (const float*)d_in[3];
    const float* b_hh  = (const float*)d_in[4];
    float* out = (float*)d_out;

    float* xproj_ptr = nullptr;
    cudaGetSymbolAddress((void**)&xproj_ptr, g_xproj);

    init_kernel<<<128, 256>>>();
    {
        dim3 grid(G3 / 128, (BB * TT) / 128);
        xproj_kernel<<<grid, 256>>>(h_enc, W_ih, b_ih, xproj_ptr);
    }
    gru_scan_kernel<<<GRID_SCAN, 256>>>(W_hh, b_hh, out);
}

// round 6
// speedup vs baseline: 2.5758x; 2.5758x over previous
#include <cuda_runtime.h>
#include <cuda_bf16.h>
#include <math.h>

// Problem constants
#define BB 64
#define TT 1000
#define NN 512
#define G3 1536
#define GRID_SCAN 128

// ---------------------------------------------------------------------------
// f32x2 packed-FMA helpers (PTX-only; ptxas never auto-fuses)
// ---------------------------------------------------------------------------
__device__ __forceinline__ unsigned long long dup2(float x) {
    unsigned long long r;
    asm("mov.b64 %0, {%1, %1};" : "=l"(r) : "f"(x));
    return r;
}
__device__ __forceinline__ void fma2(unsigned long long& d,
                                     unsigned long long a,
                                     unsigned long long b) {
    asm("fma.rn.f32x2 %0, %1, %2, %0;" : "+l"(d) : "l"(a), "l"(b));
}
__device__ __forceinline__ float2 unpack2(unsigned long long v) {
    float2 f;
    asm("mov.b64 {%0, %1}, %2;" : "=f"(f.x), "=f"(f.y) : "l"(v));
    return f;
}

// ---------------------------------------------------------------------------
// Scratch. CRITICAL: barrier counter and generation flag live on SEPARATE
// 128B L2 lines. When they shared a line, 127 spinning pollers serialized
// against the arrival RMWs at the LTS (~18us/step barrier).
// ---------------------------------------------------------------------------
struct __align__(128) Pad128 { unsigned v; unsigned pad[31]; };
__device__ Pad128   g_count;                        // arrivals (RMW line)
__device__ Pad128   g_gen;                          // generation (read-mostly line)
__device__ float    g_xproj[(size_t)BB * TT * G3];  // [B][T][3N]
__device__ float    g_ht[2][NN * BB];               // transposed hidden [k][b]

// ---------------------------------------------------------------------------
// Kernel 1: x_proj = h_enc @ W_ih^T + b_ih. 128x128x16 tiles, 8x8 microtile,
// f32x2-packed j-dimension. Block (0,0) additionally resets barrier + h0
// (must happen every graph replay; runs alongside its GEMM tile).
// ---------------------------------------------------------------------------
__global__ void __launch_bounds__(256) xproj_kernel(
    const float* __restrict__ A,     // [64000][512]
    const float* __restrict__ Wih,   // [1536][512]
    const float* __restrict__ bih,   // [1536]
    float* __restrict__ C)           // [64000][1536]
{
    __shared__ float As[16][128];
    __shared__ float Bs[16][128];

    const int tid   = threadIdx.x;
    const int mBase = blockIdx.y * 128;
    const int nBase = blockIdx.x * 128;
    const int tx = tid & 15;
    const int ty = tid >> 4;

    // Folded init (replaces init_kernel): reset barrier, zero h0.
    if (blockIdx.x == 0 && blockIdx.y == 0) {
        if (tid == 0) { g_count.v = 0u; g_gen.v = 0u; }
        for (int j = tid; j < NN * BB; j += 256) g_ht[0][j] = 0.0f;
    }

    unsigned long long acc2[8][4];
#pragma unroll
    for (int i = 0; i < 8; i++)
#pragma unroll
        for (int j = 0; j < 4; j++) acc2[i][j] = 0ull;

    const int lr = tid >> 2;
    const int lk = (tid & 3) << 2;
    const float* Aptr = A   + (size_t)(mBase + lr) * NN + lk;
    const float* Bptr = Wih + (size_t)(nBase + lr) * NN + lk;

    for (int kt = 0; kt < NN; kt += 16) {
        const float4 a0 = *(const float4*)(Aptr + kt);
        const float4 a1 = *(const float4*)(Aptr + 64 * NN + kt);
        const float4 b0 = *(const float4*)(Bptr + kt);
        const float4 b1 = *(const float4*)(Bptr + 64 * NN + kt);
        __syncthreads();
        As[lk + 0][lr] = a0.x; As[lk + 1][lr] = a0.y; As[lk + 2][lr] = a0.z; As[lk + 3][lr] = a0.w;
        As[lk + 0][64 + lr] = a1.x; As[lk + 1][64 + lr] = a1.y; As[lk + 2][64 + lr] = a1.z; As[lk + 3][64 + lr] = a1.w;
        Bs[lk + 0][lr] = b0.x; Bs[lk + 1][lr] = b0.y; Bs[lk + 2][lr] = b0.z; Bs[lk + 3][lr] = b0.w;
        Bs[lk + 0][64 + lr] = b1.x; Bs[lk + 1][64 + lr] = b1.y; Bs[lk + 2][64 + lr] = b1.z; Bs[lk + 3][64 + lr] = b1.w;
        __syncthreads();
#pragma unroll
        for (int k = 0; k < 16; k++) {
            float af[8];
            *(float4*)&af[0] = *(const float4*)&As[k][ty * 4];
            *(float4*)&af[4] = *(const float4*)&As[k][64 + ty * 4];
            unsigned long long b2[4];
            *(uint4*)&b2[0] = *(const uint4*)&Bs[k][tx * 4];
            *(uint4*)&b2[2] = *(const uint4*)&Bs[k][64 + tx * 4];
#pragma unroll
            for (int i = 0; i < 8; i++) {
                const unsigned long long ad = dup2(af[i]);
#pragma unroll
                for (int j = 0; j < 4; j++) fma2(acc2[i][j], ad, b2[j]);
            }
        }
    }

    float bias[8];
#pragma unroll
    for (int j = 0; j < 8; j++) {
        int col = nBase + ((j < 4) ? (tx * 4 + j) : (64 + tx * 4 + (j - 4)));
        bias[j] = __ldg(&bih[col]);
    }
#pragma unroll
    for (int i = 0; i < 8; i++) {
        float a[8];
#pragma unroll
        for (int j = 0; j < 4; j++) {
            const float2 v = unpack2(acc2[i][j]);
            a[2 * j] = v.x; a[2 * j + 1] = v.y;
        }
        int row = mBase + ((i < 4) ? (ty * 4 + i) : (64 + ty * 4 + (i - 4)));
        float* cp = C + (size_t)row * G3 + nBase;
        *(float4*)(cp + tx * 4) =
            make_float4(a[0] + bias[0], a[1] + bias[1], a[2] + bias[2], a[3] + bias[3]);
        *(float4*)(cp + 64 + tx * 4) =
            make_float4(a[4] + bias[4], a[5] + bias[5], a[6] + bias[6], a[7] + bias[7]);
    }
}

// ---------------------------------------------------------------------------
// Kernel 2: persistent cooperative GRU scan (transposed h, f32x2 mainloop).
// W_hh slice stored PRE-DUPLICATED as f32x2 pairs in SMEM (48KB): inner loop
// is 1 LDG.128 + 3 LDS.64 + 6 FFMA2 per k.
// ---------------------------------------------------------------------------
__global__ void __launch_bounds__(256) gru_scan_kernel(
    const float* __restrict__ Whh,   // [1536][512]
    const float* __restrict__ bhh,   // [1536]
    float* __restrict__ out)         // [B][T][N]
{
    __shared__ unsigned long long wsd[12][514];  // duplicated W: [gate*4+jn][k]
    __shared__ float  xs[3][4][64];              // x_t: [gate][nn][b]
    __shared__ float4 red[4][3][4][16];          // partials: [kq][gate][nn][b4]
    __shared__ float  hs[4][64];                 // h_new: [nn][b]

    const int tid = threadIdx.x;
    const int n0  = blockIdx.x * 4;
    const int kq  = tid >> 6;
    const int nn  = (tid >> 4) & 3;
    const int b4  = tid & 15;

    // Load + duplicate W_hh slice once (coalesced scalar loads along k)
    for (int i = tid; i < 12 * 512; i += 256) {
        const int row = i >> 9;          // gate*4 + jn
        const int k   = i & 511;
        const int gate = row >> 2;
        const int jn   = row & 3;
        const float w = __ldg(&Whh[(size_t)(gate * NN + n0 + jn) * NN + k]);
        wsd[row][k] = dup2(w);
    }

    float bhr = 0.f, bhz = 0.f, bhn = 0.f;
    if (tid < 64) {
        const int en = tid >> 4;
        bhr = __ldg(&bhh[n0 + en]);
        bhz = __ldg(&bhh[NN + n0 + en]);
        bhn = __ldg(&bhh[2 * NN + n0 + en]);
    }

    const unsigned long long* wr = &wsd[nn][kq * 128];
    const unsigned long long* wz = &wsd[4 + nn][kq * 128];
    const unsigned long long* wn = &wsd[8 + nn][kq * 128];
    __syncthreads();

    for (int t = 0; t < TT; t++) {
        const float* hcur = g_ht[t & 1];
        float*       hnxt = g_ht[(t & 1) ^ 1];

        // Stage x_proj[:, t, slice] into SMEM (latency hidden under the GEMM)
        if (tid < 192) {
            const int grp = tid >> 6;
            const int bb  = tid & 63;
            const float4 xv = __ldg((const float4*)(
                g_xproj + (size_t)(bb * TT + t) * G3 + grp * NN + n0));
            xs[grp][0][bb] = xv.x; xs[grp][1][bb] = xv.y;
            xs[grp][2][bb] = xv.z; xs[grp][3][bb] = xv.w;
        }

        // Partial gates over this thread's k-range (f32x2 packed)
        unsigned long long ar01 = 0ull, ar23 = 0ull;
        unsigned long long az01 = 0ull, az23 = 0ull;
        unsigned long long an01 = 0ull, an23 = 0ull;
        const float* hk = hcur + kq * 128 * BB + b4 * 4;
#pragma unroll 8
        for (int k = 0; k < 128; k++) {
            const ulonglong2 hv = *(const ulonglong2*)(hk + k * BB);
            const unsigned long long w0 = wr[k];
            const unsigned long long w1 = wz[k];
            const unsigned long long w2 = wn[k];
            fma2(ar01, hv.x, w0); fma2(ar23, hv.y, w0);
            fma2(az01, hv.x, w1); fma2(az23, hv.y, w1);
            fma2(an01, hv.x, w2); fma2(an23, hv.y, w2);
        }
        {
            float2 a = unpack2(ar01), b = unpack2(ar23);
            red[kq][0][nn][b4] = make_float4(a.x, a.y, b.x, b.y);
            a = unpack2(az01); b = unpack2(az23);
            red[kq][1][nn][b4] = make_float4(a.x, a.y, b.x, b.y);
            a = unpack2(an01); b = unpack2(an23);
            red[kq][2][nn][b4] = make_float4(a.x, a.y, b.x, b.y);
        }
        __syncthreads();

        // Epilogue: 64 threads finish 4 batches each for one n-column
        if (tid < 64) {
            const int en = tid >> 4;
            const int eb = tid & 15;
            float4 ar = red[0][0][en][eb], az = red[0][1][en][eb], an = red[0][2][en][eb];
#pragma unroll
            for (int q = 1; q < 4; q++) {
                const float4 r0 = red[q][0][en][eb];
                const float4 r1 = red[q][1][en][eb];
                const float4 r2 = red[q][2][en][eb];
                ar.x += r0.x; ar.y += r0.y; ar.z += r0.z; ar.w += r0.w;
                az.x += r1.x; az.y += r1.y; az.z += r1.z; az.w += r1.w;
                an.x += r2.x; an.y += r2.y; an.z += r2.z; an.w += r2.w;
            }
            const float4 hp = *(const float4*)(hcur + (n0 + en) * BB + eb * 4);
            const float4 xr = *(const float4*)&xs[0][en][eb * 4];
            const float4 xz = *(const float4*)&xs[1][en][eb * 4];
            const float4 xn = *(const float4*)&xs[2][en][eb * 4];
            const float arr[4] = { xr.x + ar.x, xr.y + ar.y, xr.z + ar.z, xr.w + ar.w };
            const float azz[4] = { xz.x + az.x, xz.y + az.y, xz.z + az.z, xz.w + az.w };
            const float ann[4] = { an.x, an.y, an.z, an.w };
            const float xnn[4] = { xn.x, xn.y, xn.z, xn.w };
            const float hpp[4] = { hp.x, hp.y, hp.z, hp.w };
#pragma unroll
            for (int j = 0; j < 4; j++) {
                const float r  = 1.0f / (1.0f + __expf(-(arr[j] + bhr)));
                const float z  = 1.0f / (1.0f + __expf(-(azz[j] + bhz)));
                const float nv = tanhf(xnn[j] + r * (ann[j] + bhn));
                hs[en][eb * 4 + j] = (1.0f - z) * nv + z * hpp[j];
            }
        }
        __syncthreads();

        // Writeback: output (n-contiguous) + transposed h state, then release
        if (tid < 64) {
            const int b = tid;
            *(float4*)(out + (size_t)(b * TT + t) * NN + n0) =
                make_float4(hs[0][b], hs[1][b], hs[2][b], hs[3][b]);
            const int rr = tid >> 4, seg = tid & 15;
            *(float4*)(hnxt + (n0 + rr) * BB + seg * 4) = *(const float4*)&hs[rr][seg * 4];
            __threadfence();   // release h_new before barrier arrival
        }
        __syncthreads();

        // Grid barrier: arrivals RMW g_count (own line); pollers read g_gen
        // (own, read-mostly line) with light backoff.
        if (t < TT - 1) {
            if (tid == 0) {
                const unsigned target = (unsigned)(t + 1);
                const unsigned arrived = atomicAdd(&g_count.v, 1u) + 1u;
                if (arrived == target * (unsigned)GRID_SCAN) {
                    atomicExch(&g_gen.v, target);
                } else {
                    volatile unsigned* vg = &g_gen.v;
                    while (*vg < target) { __nanosleep(32); }
                }
            }
            __syncthreads();
            __threadfence();   // acquire (CCTL.IVALL): see other CTAs' h writes
        }
    }
}

// ---------------------------------------------------------------------------
// Launch
// ---------------------------------------------------------------------------
extern "C" void kernel_launch(void* const* d_in, const int* in_sizes, int n_in,
                              void* d_out, int out_size) {
    const float* h_enc = (const float*)d_in[0];
    const float* W_ih  = (const float*)d_in[1];
    const float* W_hh  = (const float*)d_in[2];
    const float* b_ih  = (const float*)d_in[3];
    const float* b_hh  = (const float*)d_in[4];
    float* out = (float*)d_out;

    float* xproj_ptr = nullptr;
    cudaGetSymbolAddress((void**)&xproj_ptr, g_xproj);

    dim3 grid(G3 / 128, (BB * TT) / 128);
    xproj_kernel<<<grid, 256>>>(h_enc, W_ih, b_ih, xproj_ptr);
    gru_scan_kernel<<<GRID_SCAN, 256>>>(W_hh, b_hh, out);
}